// round 1
// baseline (speedup 1.0000x reference)
#include <cuda_runtime.h>
#include <cuda_bf16.h>
#include <math.h>

// Problem constants
#define BB 8
#define SS 1024
#define DIN 512
#define HH 1024
#define NHEAD 16
#define HD 64
#define NLAYER 4
#define MROWS (BB * SS)   // 8192

// ---------------------------------------------------------------------------
// Scratch (device globals; no allocation allowed)
// ---------------------------------------------------------------------------
__device__ float g_h[MROWS * HH];          // 32 MB activations
__device__ float g_qkv[MROWS * 3 * HH];    // 96 MB qkv
__device__ float g_ctx[MROWS * HH];        // 32 MB attention out
__device__ float g_tmp[MROWS * HH];        // 32 MB pre-LN
__device__ float g_pool[BB * HH];          // pooled
__device__ float g_fin[BB * HH];           // final gemm out

// ---------------------------------------------------------------------------
// GEMM: C[M,N] = A[M,K] @ B[K,N] + bias (+ optional residual)
// BM=BN=128, BK=16, 256 threads, 8x8 micro-tiles.
// Requires M%128==0, N%128==0, K%16==0 (true for all calls here).
// ---------------------------------------------------------------------------
#define GBM 128
#define GBN 128
#define GBK 16

__global__ void __launch_bounds__(256) gemm_bias_kernel(
    const float* __restrict__ A, const float* __restrict__ Bm,
    const float* __restrict__ bias, const float* __restrict__ res,
    float* __restrict__ C, int M, int N, int K, int hasRes)
{
    __shared__ float As[GBK][GBM + 4];
    __shared__ float Bs[GBK][GBN + 4];

    const int t  = threadIdx.x;
    const int tx = t % 16;
    const int ty = t / 16;
    const int m0 = blockIdx.y * GBM;
    const int n0 = blockIdx.x * GBN;

    const int arow = t / 4;          // 0..63
    const int acol = (t % 4) * 4;    // 0,4,8,12
    const int brow = t / 32;         // 0..7
    const int bcol = (t % 32) * 4;   // 0..124

    float acc[8][8];
#pragma unroll
    for (int i = 0; i < 8; i++)
#pragma unroll
        for (int j = 0; j < 8; j++) acc[i][j] = 0.0f;

    for (int k0 = 0; k0 < K; k0 += GBK) {
        // load A tile (transposed into As[k][m])
#pragma unroll
        for (int r = 0; r < 2; r++) {
            const float4 v = *(const float4*)&A[(size_t)(m0 + arow + r * 64) * K + k0 + acol];
            As[acol + 0][arow + r * 64] = v.x;
            As[acol + 1][arow + r * 64] = v.y;
            As[acol + 2][arow + r * 64] = v.z;
            As[acol + 3][arow + r * 64] = v.w;
        }
        // load B tile (direct)
#pragma unroll
        for (int r = 0; r < 2; r++) {
            const float4 v = *(const float4*)&Bm[(size_t)(k0 + brow + r * 8) * N + n0 + bcol];
            *(float4*)&Bs[brow + r * 8][bcol] = v;
        }
        __syncthreads();

#pragma unroll
        for (int k = 0; k < GBK; k++) {
            float a[8], b[8];
            *(float4*)&a[0] = *(const float4*)&As[k][ty * 8];
            *(float4*)&a[4] = *(const float4*)&As[k][ty * 8 + 4];
            *(float4*)&b[0] = *(const float4*)&Bs[k][tx * 8];
            *(float4*)&b[4] = *(const float4*)&Bs[k][tx * 8 + 4];
#pragma unroll
            for (int i = 0; i < 8; i++)
#pragma unroll
                for (int j = 0; j < 8; j++)
                    acc[i][j] += a[i] * b[j];
        }
        __syncthreads();
    }

    // epilogue
#pragma unroll
    for (int i = 0; i < 8; i++) {
        const int m = m0 + ty * 8 + i;
#pragma unroll
        for (int j = 0; j < 8; j += 4) {
            const int n = n0 + tx * 8 + j;
            float4 o;
            o.x = acc[i][j + 0] + bias[n + 0];
            o.y = acc[i][j + 1] + bias[n + 1];
            o.z = acc[i][j + 2] + bias[n + 2];
            o.w = acc[i][j + 3] + bias[n + 3];
            if (hasRes) {
                const float4 r4 = *(const float4*)&res[(size_t)m * N + n];
                o.x += r4.x; o.y += r4.y; o.z += r4.z; o.w += r4.w;
            }
            *(float4*)&C[(size_t)m * N + n] = o;
        }
    }
}

// ---------------------------------------------------------------------------
// Fused flash-style attention (fp32).
// qkv: [B, S, 3*H] where within a row: [3][NH][HD].
// ctx: [B, S, NH*HD]
// grid (S/64, NH, B), 256 threads, dynamic smem.
// ---------------------------------------------------------------------------
#define ASTR 68   // padded row stride (floats)

__global__ void __launch_bounds__(256) attn_kernel(
    const float* __restrict__ qkv, float* __restrict__ ctx)
{
    extern __shared__ float sm[];
    float* Qs   = sm;                  // [d][q]  64 x ASTR
    float* Ks   = Qs + 64 * ASTR;      // [d][k]
    float* Vs   = Ks + 64 * ASTR;      // [k][d]
    float* Ps   = Vs + 64 * ASTR;      // [k][q]  (scores / probs, transposed)
    float* scl  = Ps + 64 * ASTR;      // [64]
    float* lrow = scl + 64;            // [64]

    const int b  = blockIdx.z;
    const int nh = blockIdx.y;
    const int qt = blockIdx.x;
    const int t  = threadIdx.x;
    const int tx = t % 16;
    const int ty = t / 16;

    const float SC = 0.125f;           // HD^-0.5

    const float* base = qkv + (size_t)b * SS * (3 * HH) + nh * HD;

    // load Q tile transposed: Qs[d][q]
    {
        const int q = t / 4;
        const int dbase = (t % 4) * 16;
        const float* src = base + (size_t)(qt * 64 + q) * (3 * HH);
#pragma unroll
        for (int dd = 0; dd < 16; dd += 4) {
            const float4 v = *(const float4*)&src[dbase + dd];
            Qs[(dbase + dd + 0) * ASTR + q] = v.x;
            Qs[(dbase + dd + 1) * ASTR + q] = v.y;
            Qs[(dbase + dd + 2) * ASTR + q] = v.z;
            Qs[(dbase + dd + 3) * ASTR + q] = v.w;
        }
    }

    float O[4][4];
#pragma unroll
    for (int i = 0; i < 4; i++)
#pragma unroll
        for (int j = 0; j < 4; j++) O[i][j] = 0.0f;

    // softmax-phase per-thread state: row r = t/4, part = t%4
    const int r    = t / 4;
    const int part = t % 4;
    float m_run = -INFINITY;
    float l_run = 0.0f;

    for (int kt = 0; kt < SS / 64; kt++) {
        __syncthreads();  // protect Ks/Vs/Ps reuse from previous iteration
        // load K (transposed) and V (direct) tiles
        {
            const int kk = t / 4;
            const int dbase = (t % 4) * 16;
            const float* srcK = base + (size_t)(kt * 64 + kk) * (3 * HH) + HH;
            const float* srcV = base + (size_t)(kt * 64 + kk) * (3 * HH) + 2 * HH;
#pragma unroll
            for (int dd = 0; dd < 16; dd += 4) {
                const float4 v = *(const float4*)&srcK[dbase + dd];
                Ks[(dbase + dd + 0) * ASTR + kk] = v.x;
                Ks[(dbase + dd + 1) * ASTR + kk] = v.y;
                Ks[(dbase + dd + 2) * ASTR + kk] = v.z;
                Ks[(dbase + dd + 3) * ASTR + kk] = v.w;
                const float4 w = *(const float4*)&srcV[dbase + dd];
                *(float4*)&Vs[kk * ASTR + dbase + dd] = w;
            }
        }
        __syncthreads();

        // scores: S[q=ty*4+i][k=tx*4+j]
        float s[4][4];
#pragma unroll
        for (int i = 0; i < 4; i++)
#pragma unroll
            for (int j = 0; j < 4; j++) s[i][j] = 0.0f;

#pragma unroll 8
        for (int d = 0; d < 64; d++) {
            float qv[4], kv[4];
            *(float4*)&qv[0] = *(const float4*)&Qs[d * ASTR + ty * 4];
            *(float4*)&kv[0] = *(const float4*)&Ks[d * ASTR + tx * 4];
#pragma unroll
            for (int i = 0; i < 4; i++)
#pragma unroll
                for (int j = 0; j < 4; j++)
                    s[i][j] += qv[i] * kv[j];
        }
        // write transposed, scaled: Ps[k][q]
#pragma unroll
        for (int i = 0; i < 4; i++)
#pragma unroll
            for (int j = 0; j < 4; j++)
                Ps[(tx * 4 + j) * ASTR + (ty * 4 + i)] = s[i][j] * SC;
        __syncthreads();

        // online softmax (4 threads per row, 16 cols each)
        float mloc = -INFINITY;
#pragma unroll
        for (int c = 0; c < 16; c++) {
            const float v = Ps[(part * 16 + c) * ASTR + r];
            mloc = fmaxf(mloc, v);
        }
        mloc = fmaxf(mloc, __shfl_xor_sync(0xffffffffu, mloc, 1));
        mloc = fmaxf(mloc, __shfl_xor_sync(0xffffffffu, mloc, 2));
        const float mnew = fmaxf(m_run, mloc);
        const float sc   = __expf(m_run - mnew);
        float lpart = 0.0f;
#pragma unroll
        for (int c = 0; c < 16; c++) {
            const int idx = (part * 16 + c) * ASTR + r;
            const float p = __expf(Ps[idx] - mnew);
            Ps[idx] = p;
            lpart += p;
        }
        l_run = l_run * sc + lpart;
        m_run = mnew;
        if (part == 0) scl[r] = sc;
        __syncthreads();

        // O = O*scale + P @ V   (thread: rows q=ty*4+i, cols d=tx*4+j)
        float rs[4];
#pragma unroll
        for (int i = 0; i < 4; i++) rs[i] = scl[ty * 4 + i];
#pragma unroll
        for (int i = 0; i < 4; i++)
#pragma unroll
            for (int j = 0; j < 4; j++) O[i][j] *= rs[i];

#pragma unroll 8
        for (int k = 0; k < 64; k++) {
            float pv[4], vv[4];
            *(float4*)&pv[0] = *(const float4*)&Ps[k * ASTR + ty * 4];
            *(float4*)&vv[0] = *(const float4*)&Vs[k * ASTR + tx * 4];
#pragma unroll
            for (int i = 0; i < 4; i++)
#pragma unroll
                for (int j = 0; j < 4; j++)
                    O[i][j] += pv[i] * vv[j];
        }
    }

    // finalize l per row
    float lf = l_run;
    lf += __shfl_xor_sync(0xffffffffu, lf, 1);
    lf += __shfl_xor_sync(0xffffffffu, lf, 2);
    if (part == 0) lrow[r] = lf;
    __syncthreads();

    // write ctx
#pragma unroll
    for (int i = 0; i < 4; i++) {
        const int q = qt * 64 + ty * 4 + i;
        const float inv = 1.0f / lrow[ty * 4 + i];
        float4 o;
        o.x = O[i][0] * inv;
        o.y = O[i][1] * inv;
        o.z = O[i][2] * inv;
        o.w = O[i][3] * inv;
        *(float4*)&ctx[((size_t)b * SS + q) * HH + nh * HD + tx * 4] = o;
    }
}

// ---------------------------------------------------------------------------
// LayerNorm over rows of 1024.  grid = nrows blocks, 256 threads.
// ---------------------------------------------------------------------------
__global__ void __launch_bounds__(256) ln_kernel(
    const float* __restrict__ in, const float* __restrict__ gamma,
    const float* __restrict__ beta, float* __restrict__ out)
{
    const int row = blockIdx.x;
    const float* x = in + (size_t)row * HH;
    __shared__ float red[256];
    __shared__ float s_mean, s_rstd;
    const int tid = threadIdx.x;

    float s = 0.0f;
#pragma unroll
    for (int i = tid; i < HH; i += 256) s += x[i];
    red[tid] = s;
    __syncthreads();
    for (int off = 128; off > 0; off >>= 1) {
        if (tid < off) red[tid] += red[tid + off];
        __syncthreads();
    }
    if (tid == 0) s_mean = red[0] * (1.0f / HH);
    __syncthreads();
    const float mean = s_mean;

    float v = 0.0f;
#pragma unroll
    for (int i = tid; i < HH; i += 256) {
        const float d = x[i] - mean;
        v += d * d;
    }
    red[tid] = v;
    __syncthreads();
    for (int off = 128; off > 0; off >>= 1) {
        if (tid < off) red[tid] += red[tid + off];
        __syncthreads();
    }
    if (tid == 0) s_rstd = rsqrtf(red[0] * (1.0f / HH) + 1e-5f);
    __syncthreads();
    const float rstd = s_rstd;

#pragma unroll
    for (int i = tid; i < HH; i += 256)
        out[(size_t)row * HH + i] = (x[i] - mean) * rstd * gamma[i] + beta[i];
}

// ---------------------------------------------------------------------------
// Mean pool over S.  grid (HH/256, B)
// ---------------------------------------------------------------------------
__global__ void __launch_bounds__(256) pool_kernel(
    const float* __restrict__ h, float* __restrict__ pooled)
{
    const int j = blockIdx.x * 256 + threadIdx.x;
    const int b = blockIdx.y;
    float s = 0.0f;
#pragma unroll 8
    for (int ss = 0; ss < SS; ss++)
        s += h[((size_t)b * SS + ss) * HH + j];
    pooled[b * HH + j] = s * (1.0f / SS);
}

// ---------------------------------------------------------------------------
// Final small GEMM: out[b][col] = pooled[b] . W[:,col] + bias[col]
// grid (HH/256, B)
// ---------------------------------------------------------------------------
__global__ void __launch_bounds__(256) final_gemm_kernel(
    const float* __restrict__ pooled, const float* __restrict__ W,
    const float* __restrict__ bias, float* __restrict__ out)
{
    __shared__ float pr[HH];
    const int b   = blockIdx.y;
    const int col = blockIdx.x * 256 + threadIdx.x;
    for (int i = threadIdx.x; i < HH; i += 256) pr[i] = pooled[b * HH + i];
    __syncthreads();
    float s = bias[col];
#pragma unroll 8
    for (int k = 0; k < HH; k++)
        s += pr[k] * W[(size_t)k * HH + col];
    out[b * HH + col] = s;
}

// ---------------------------------------------------------------------------
// Launch
// ---------------------------------------------------------------------------
extern "C" void kernel_launch(void* const* d_in, const int* in_sizes, int n_in,
                              void* d_out, int out_size)
{
    const float* x     = (const float*)d_in[0];
    const float* W_in  = (const float*)d_in[1];
    const float* b_in  = (const float*)d_in[2];
    const float* W_qkv = (const float*)d_in[3];
    const float* b_qkv = (const float*)d_in[4];
    const float* W_o   = (const float*)d_in[5];
    const float* b_o   = (const float*)d_in[6];
    const float* g1    = (const float*)d_in[7];
    const float* be1   = (const float*)d_in[8];
    const float* W_out = (const float*)d_in[9];
    const float* b_out = (const float*)d_in[10];
    const float* g2    = (const float*)d_in[11];
    const float* be2   = (const float*)d_in[12];
    float* out = (float*)d_out;

    float *h, *qkv, *ctx, *tmp, *pool, *fin;
    cudaGetSymbolAddress((void**)&h,    g_h);
    cudaGetSymbolAddress((void**)&qkv,  g_qkv);
    cudaGetSymbolAddress((void**)&ctx,  g_ctx);
    cudaGetSymbolAddress((void**)&tmp,  g_tmp);
    cudaGetSymbolAddress((void**)&pool, g_pool);
    cudaGetSymbolAddress((void**)&fin,  g_fin);

    const int attn_smem = (4 * 64 * ASTR + 128) * sizeof(float);
    cudaFuncSetAttribute(attn_kernel, cudaFuncAttributeMaxDynamicSharedMemorySize, attn_smem);

    // 1. input projection: h = x @ W_in + b_in   (M=8192, K=512, N=1024)
    gemm_bias_kernel<<<dim3(HH / GBN, MROWS / GBM), 256>>>(
        x, W_in, b_in, nullptr, h, MROWS, HH, DIN, 0);

    // 2. layers
    for (int l = 0; l < NLAYER; l++) {
        const float* Wq = W_qkv + (size_t)l * HH * 3 * HH;
        const float* bq = b_qkv + (size_t)l * 3 * HH;
        const float* Wo = W_o + (size_t)l * HH * HH;
        const float* bo = b_o + (size_t)l * HH;
        const float* gg = g1 + (size_t)l * HH;
        const float* bb = be1 + (size_t)l * HH;

        // qkv = h @ Wq + bq   (M=8192, K=1024, N=3072)
        gemm_bias_kernel<<<dim3(3 * HH / GBN, MROWS / GBM), 256>>>(
            h, Wq, bq, nullptr, qkv, MROWS, 3 * HH, HH, 0);

        // attention
        attn_kernel<<<dim3(SS / 64, NHEAD, BB), 256, attn_smem>>>(qkv, ctx);

        // o-proj + residual: tmp = ctx @ Wo + bo + h
        gemm_bias_kernel<<<dim3(HH / GBN, MROWS / GBM), 256>>>(
            ctx, Wo, bo, h, tmp, MROWS, HH, HH, 1);

        // layernorm -> h
        ln_kernel<<<MROWS, 256>>>(tmp, gg, bb, h);
    }

    // 3. mean pool
    pool_kernel<<<dim3(HH / 256, BB), 256>>>(h, pool);

    // 4. final projection + LN
    final_gemm_kernel<<<dim3(HH / 256, BB), 256>>>(pool, W_out, b_out, fin);
    ln_kernel<<<BB, 256>>>(fin, g2, be2, out);
}

// round 3
// speedup vs baseline: 1.3694x; 1.3694x over previous
#include <cuda_runtime.h>
#include <cuda_bf16.h>
#include <math.h>
#include <stdint.h>

// Problem constants
#define BB 8
#define SS 1024
#define DIN 512
#define HH 1024
#define NHEAD 16
#define HD 64
#define NLAYER 4
#define MROWS (BB * SS)   // 8192

// ---------------------------------------------------------------------------
// Scratch (device globals; no allocation allowed)
// ---------------------------------------------------------------------------
__device__ float g_h[MROWS * HH];
__device__ float g_qkv[MROWS * 3 * HH];
__device__ float g_ctx[MROWS * HH];
__device__ float g_tmp[MROWS * HH];
__device__ float g_pool[BB * HH];
__device__ float g_fin[BB * HH];

// bf16 split buffers
__device__ __nv_bfloat16 g_ah[MROWS * HH];
__device__ __nv_bfloat16 g_al[MROWS * HH];

#define W_TOTAL (DIN * HH + NLAYER * HH * 3 * HH + NLAYER * HH * HH)
__device__ __nv_bfloat16 g_wh[W_TOTAL];
__device__ __nv_bfloat16 g_wl[W_TOTAL];

// ---------------------------------------------------------------------------
// Small PTX wrappers (all architecture-portable: sm_80+)
// ---------------------------------------------------------------------------
__device__ __forceinline__ uint32_t smem_u32(const void* p) {
    uint32_t a;
    asm("{ .reg .u64 t; cvta.to.shared.u64 t, %1; cvt.u32.u64 %0, t; }"
        : "=r"(a) : "l"(p));
    return a;
}

__device__ __forceinline__ void cp_async16(uint32_t dst, const void* src) {
    asm volatile("cp.async.cg.shared.global [%0], [%1], 16;"
                 :: "r"(dst), "l"(src));
}
__device__ __forceinline__ void cp_commit() {
    asm volatile("cp.async.commit_group;");
}
template <int N>
__device__ __forceinline__ void cp_wait() {
    asm volatile("cp.async.wait_group %0;" :: "n"(N));
}

__device__ __forceinline__ void ldsm_x4(uint32_t addr, uint32_t r[4]) {
    asm volatile("ldmatrix.sync.aligned.m8n8.x4.shared.b16 {%0,%1,%2,%3}, [%4];"
                 : "=r"(r[0]), "=r"(r[1]), "=r"(r[2]), "=r"(r[3]) : "r"(addr));
}

__device__ __forceinline__ void mma_bf16(
    float c[4], const uint32_t a[4], const uint32_t b0, const uint32_t b1)
{
    asm volatile(
        "mma.sync.aligned.m16n8k16.row.col.f32.bf16.bf16.f32 "
        "{%0,%1,%2,%3}, {%4,%5,%6,%7}, {%8,%9}, {%0,%1,%2,%3};"
        : "+f"(c[0]), "+f"(c[1]), "+f"(c[2]), "+f"(c[3])
        : "r"(a[0]), "r"(a[1]), "r"(a[2]), "r"(a[3]), "r"(b0), "r"(b1));
}

// ---------------------------------------------------------------------------
// Weight transpose + split: W[K,N] fp32 -> Wt hi/lo [N,K] bf16
// ---------------------------------------------------------------------------
__global__ void transpose_split_kernel(
    const float* __restrict__ W,
    __nv_bfloat16* __restrict__ Th, __nv_bfloat16* __restrict__ Tl,
    int K, int N)
{
    __shared__ float tile[32][33];
    const int k0 = blockIdx.y * 32;
    const int n0 = blockIdx.x * 32;
    const int tx = threadIdx.x;
    const int ty = threadIdx.y;

#pragma unroll
    for (int r = 0; r < 32; r += 8)
        tile[ty + r][tx] = W[(size_t)(k0 + ty + r) * N + n0 + tx];
    __syncthreads();

#pragma unroll
    for (int r = 0; r < 32; r += 8) {
        const float v = tile[tx][ty + r];
        const __nv_bfloat16 h = __float2bfloat16(v);
        const float lo = v - __bfloat162float(h);
        const size_t o = (size_t)(n0 + ty + r) * K + k0 + tx;
        Th[o] = h;
        Tl[o] = __float2bfloat16(lo);
    }
}

// ---------------------------------------------------------------------------
// Activation split: fp32 -> (bf16 hi, bf16 lo)
// ---------------------------------------------------------------------------
__global__ void split_act_kernel(
    const float* __restrict__ in,
    __nv_bfloat16* __restrict__ hi, __nv_bfloat16* __restrict__ lo, int n4)
{
    const int i = blockIdx.x * 256 + threadIdx.x;
    if (i >= n4) return;
    const float4 v = ((const float4*)in)[i];
    const __nv_bfloat16 h0 = __float2bfloat16(v.x);
    const __nv_bfloat16 h1 = __float2bfloat16(v.y);
    const __nv_bfloat16 h2 = __float2bfloat16(v.z);
    const __nv_bfloat16 h3 = __float2bfloat16(v.w);
    __nv_bfloat162 ha; ha.x = h0; ha.y = h1;
    __nv_bfloat162 hb; hb.x = h2; hb.y = h3;
    ((__nv_bfloat162*)hi)[i * 2]     = ha;
    ((__nv_bfloat162*)hi)[i * 2 + 1] = hb;
    __nv_bfloat162 la, lb;
    la.x = __float2bfloat16(v.x - __bfloat162float(h0));
    la.y = __float2bfloat16(v.y - __bfloat162float(h1));
    lb.x = __float2bfloat16(v.z - __bfloat162float(h2));
    lb.y = __float2bfloat16(v.w - __bfloat162float(h3));
    ((__nv_bfloat162*)lo)[i * 2]     = la;
    ((__nv_bfloat162*)lo)[i * 2 + 1] = lb;
}

// ---------------------------------------------------------------------------
// Split-bf16 tensor-core GEMM via mma.sync (HMMA):
//   C[M,N] = (Ah+Al)[M,K] @ (Bh+Bl)[N,K]^T + bias (+ res)
// CTA 128x128, K-chunk 32, 256 threads (8 warps, each 64x32).
// Double-buffered cp.async smem; padded stride for conflict-free ldmatrix.
// ---------------------------------------------------------------------------
#define MBM 128
#define MBN 128
#define MBK 32
#define MSTR 40                               // bf16 elems per smem row (80B)
#define MTILE (128 * MSTR * 2)                // 10240 B per tile
#define MSTAGE (4 * MTILE)                    // 40960 B
#define MM_SMEM (2 * MSTAGE)                  // 81920 B

__global__ void __launch_bounds__(256)
mma_gemm_kernel(
    const __nv_bfloat16* __restrict__ Ah, const __nv_bfloat16* __restrict__ Al,
    const __nv_bfloat16* __restrict__ Bh, const __nv_bfloat16* __restrict__ Bl,
    const float* __restrict__ bias, const float* __restrict__ res,
    float* __restrict__ C, int M, int N, int K, int hasRes)
{
    extern __shared__ __align__(16) char smem[];
    const uint32_t sbase = smem_u32(smem);

    const int t    = threadIdx.x;
    const int wid  = t >> 5;
    const int lane = t & 31;
    const int m0 = blockIdx.y * MBM;
    const int n0 = blockIdx.x * MBN;

    const int warp_m = (wid >> 2) * 64;   // 0 or 64
    const int warp_n = (wid & 3) * 32;    // 0,32,64,96

    // copy indexing: each thread: row = t/2, two 16B quads
    const int crow  = t >> 1;
    const int cq    = (t & 1) * 2;

    const __nv_bfloat16* gsrc[4];
    gsrc[0] = Ah + (size_t)(m0 + crow) * K;
    gsrc[1] = Al + (size_t)(m0 + crow) * K;
    gsrc[2] = Bh + (size_t)(n0 + crow) * K;
    gsrc[3] = Bl + (size_t)(n0 + crow) * K;
    const uint32_t sdst_row = crow * (MSTR * 2);

    const int nc = K / MBK;

    // prologue: stage 0
    {
        const int k0 = 0;
#pragma unroll
        for (int tl = 0; tl < 4; tl++) {
            const uint32_t d = sbase + tl * MTILE + sdst_row;
            cp_async16(d + (cq + 0) * 16, gsrc[tl] + k0 + (cq + 0) * 8);
            cp_async16(d + (cq + 1) * 16, gsrc[tl] + k0 + (cq + 1) * 8);
        }
        cp_commit();
    }

    float acc[4][4][4];
#pragma unroll
    for (int mi = 0; mi < 4; mi++)
#pragma unroll
        for (int ni = 0; ni < 4; ni++)
#pragma unroll
            for (int r = 0; r < 4; r++) acc[mi][ni][r] = 0.0f;

    // ldmatrix row/col (within tile) for this lane
    const int lrow = lane & 15;
    const int lcolq = (lane >> 4) << 3;       // 0 or 8

    for (int c = 0; c < nc; c++) {
        const int st = c & 1;
        if (c + 1 < nc) {
            const int k0 = (c + 1) * MBK;
            const uint32_t so = ((c + 1) & 1) * MSTAGE;
#pragma unroll
            for (int tl = 0; tl < 4; tl++) {
                const uint32_t d = sbase + so + tl * MTILE + sdst_row;
                cp_async16(d + (cq + 0) * 16, gsrc[tl] + k0 + (cq + 0) * 8);
                cp_async16(d + (cq + 1) * 16, gsrc[tl] + k0 + (cq + 1) * 8);
            }
            cp_commit();
            cp_wait<1>();
        } else {
            cp_wait<0>();
        }
        __syncthreads();

        const uint32_t sAh = sbase + st * MSTAGE + 0 * MTILE;
        const uint32_t sAl = sbase + st * MSTAGE + 1 * MTILE;
        const uint32_t sBh = sbase + st * MSTAGE + 2 * MTILE;
        const uint32_t sBl = sbase + st * MSTAGE + 3 * MTILE;

#pragma unroll
        for (int ks = 0; ks < 2; ks++) {
            const int col = ks * 16 + lcolq;
            uint32_t afh[4][4], afl[4][4];
#pragma unroll
            for (int mi = 0; mi < 4; mi++) {
                const uint32_t off =
                    (uint32_t)(warp_m + mi * 16 + lrow) * (MSTR * 2) + col * 2;
                ldsm_x4(sAh + off, afh[mi]);
                ldsm_x4(sAl + off, afl[mi]);
            }
            uint32_t bfh[4][2], bfl[4][2];
#pragma unroll
            for (int n2 = 0; n2 < 2; n2++) {
                const uint32_t off =
                    (uint32_t)(warp_n + n2 * 16 + lrow) * (MSTR * 2) + col * 2;
                uint32_t r4[4];
                ldsm_x4(sBh + off, r4);
                bfh[n2 * 2 + 0][0] = r4[0]; bfh[n2 * 2 + 1][0] = r4[1];
                bfh[n2 * 2 + 0][1] = r4[2]; bfh[n2 * 2 + 1][1] = r4[3];
                ldsm_x4(sBl + off, r4);
                bfl[n2 * 2 + 0][0] = r4[0]; bfl[n2 * 2 + 1][0] = r4[1];
                bfl[n2 * 2 + 0][1] = r4[2]; bfl[n2 * 2 + 1][1] = r4[3];
            }
#pragma unroll
            for (int mi = 0; mi < 4; mi++)
#pragma unroll
                for (int ni = 0; ni < 4; ni++) {
                    mma_bf16(acc[mi][ni], afh[mi], bfh[ni][0], bfh[ni][1]);
                    mma_bf16(acc[mi][ni], afh[mi], bfl[ni][0], bfl[ni][1]);
                    mma_bf16(acc[mi][ni], afl[mi], bfh[ni][0], bfh[ni][1]);
                }
        }
        __syncthreads();
    }

    // epilogue: fragment layout m16n8 f32: d0,d1 -> row g, cols 2*tg, 2*tg+1;
    // d2,d3 -> row g+8
    const int g  = lane >> 2;
    const int tg = lane & 3;
#pragma unroll
    for (int mi = 0; mi < 4; mi++) {
#pragma unroll
        for (int ni = 0; ni < 4; ni++) {
            const int colg = n0 + warp_n + ni * 8 + tg * 2;
            const float bx = bias[colg], by = bias[colg + 1];
            const int r0 = m0 + warp_m + mi * 16 + g;
            const int r1 = r0 + 8;
            float2 o0, o1;
            o0.x = acc[mi][ni][0] + bx; o0.y = acc[mi][ni][1] + by;
            o1.x = acc[mi][ni][2] + bx; o1.y = acc[mi][ni][3] + by;
            if (hasRes) {
                const float2 v0 = *(const float2*)(res + (size_t)r0 * N + colg);
                const float2 v1 = *(const float2*)(res + (size_t)r1 * N + colg);
                o0.x += v0.x; o0.y += v0.y;
                o1.x += v1.x; o1.y += v1.y;
            }
            *(float2*)(C + (size_t)r0 * N + colg) = o0;
            *(float2*)(C + (size_t)r1 * N + colg) = o1;
        }
    }
}

// ---------------------------------------------------------------------------
// Fused flash-style attention (fp32). Unchanged from R1 (passed).
// ---------------------------------------------------------------------------
#define ASTR 68

__global__ void __launch_bounds__(256) attn_kernel(
    const float* __restrict__ qkv, float* __restrict__ ctx)
{
    extern __shared__ float sm[];
    float* Qs   = sm;
    float* Ks   = Qs + 64 * ASTR;
    float* Vs   = Ks + 64 * ASTR;
    float* Ps   = Vs + 64 * ASTR;
    float* scl  = Ps + 64 * ASTR;
    float* lrow = scl + 64;

    const int b  = blockIdx.z;
    const int nh = blockIdx.y;
    const int qt = blockIdx.x;
    const int t  = threadIdx.x;
    const int tx = t % 16;
    const int ty = t / 16;

    const float SC = 0.125f;
    const float* base = qkv + (size_t)b * SS * (3 * HH) + nh * HD;

    {
        const int q = t / 4;
        const int dbase = (t % 4) * 16;
        const float* src = base + (size_t)(qt * 64 + q) * (3 * HH);
#pragma unroll
        for (int dd = 0; dd < 16; dd += 4) {
            const float4 v = *(const float4*)&src[dbase + dd];
            Qs[(dbase + dd + 0) * ASTR + q] = v.x;
            Qs[(dbase + dd + 1) * ASTR + q] = v.y;
            Qs[(dbase + dd + 2) * ASTR + q] = v.z;
            Qs[(dbase + dd + 3) * ASTR + q] = v.w;
        }
    }

    float O[4][4];
#pragma unroll
    for (int i = 0; i < 4; i++)
#pragma unroll
        for (int j = 0; j < 4; j++) O[i][j] = 0.0f;

    const int r    = t / 4;
    const int part = t % 4;
    float m_run = -INFINITY;
    float l_run = 0.0f;

    for (int kt = 0; kt < SS / 64; kt++) {
        __syncthreads();
        {
            const int kk = t / 4;
            const int dbase = (t % 4) * 16;
            const float* srcK = base + (size_t)(kt * 64 + kk) * (3 * HH) + HH;
            const float* srcV = base + (size_t)(kt * 64 + kk) * (3 * HH) + 2 * HH;
#pragma unroll
            for (int dd = 0; dd < 16; dd += 4) {
                const float4 v = *(const float4*)&srcK[dbase + dd];
                Ks[(dbase + dd + 0) * ASTR + kk] = v.x;
                Ks[(dbase + dd + 1) * ASTR + kk] = v.y;
                Ks[(dbase + dd + 2) * ASTR + kk] = v.z;
                Ks[(dbase + dd + 3) * ASTR + kk] = v.w;
                const float4 w = *(const float4*)&srcV[dbase + dd];
                *(float4*)&Vs[kk * ASTR + dbase + dd] = w;
            }
        }
        __syncthreads();

        float s[4][4];
#pragma unroll
        for (int i = 0; i < 4; i++)
#pragma unroll
            for (int j = 0; j < 4; j++) s[i][j] = 0.0f;

#pragma unroll 8
        for (int d = 0; d < 64; d++) {
            float qv[4], kv[4];
            *(float4*)&qv[0] = *(const float4*)&Qs[d * ASTR + ty * 4];
            *(float4*)&kv[0] = *(const float4*)&Ks[d * ASTR + tx * 4];
#pragma unroll
            for (int i = 0; i < 4; i++)
#pragma unroll
                for (int j = 0; j < 4; j++)
                    s[i][j] += qv[i] * kv[j];
        }
#pragma unroll
        for (int i = 0; i < 4; i++)
#pragma unroll
            for (int j = 0; j < 4; j++)
                Ps[(tx * 4 + j) * ASTR + (ty * 4 + i)] = s[i][j] * SC;
        __syncthreads();

        float mloc = -INFINITY;
#pragma unroll
        for (int c = 0; c < 16; c++) {
            const float v = Ps[(part * 16 + c) * ASTR + r];
            mloc = fmaxf(mloc, v);
        }
        mloc = fmaxf(mloc, __shfl_xor_sync(0xffffffffu, mloc, 1));
        mloc = fmaxf(mloc, __shfl_xor_sync(0xffffffffu, mloc, 2));
        const float mnew = fmaxf(m_run, mloc);
        const float sc   = __expf(m_run - mnew);
        float lpart = 0.0f;
#pragma unroll
        for (int c = 0; c < 16; c++) {
            const int idx = (part * 16 + c) * ASTR + r;
            const float p = __expf(Ps[idx] - mnew);
            Ps[idx] = p;
            lpart += p;
        }
        l_run = l_run * sc + lpart;
        m_run = mnew;
        if (part == 0) scl[r] = sc;
        __syncthreads();

        float rs[4];
#pragma unroll
        for (int i = 0; i < 4; i++) rs[i] = scl[ty * 4 + i];
#pragma unroll
        for (int i = 0; i < 4; i++)
#pragma unroll
            for (int j = 0; j < 4; j++) O[i][j] *= rs[i];

#pragma unroll 8
        for (int k = 0; k < 64; k++) {
            float pv[4], vv[4];
            *(float4*)&pv[0] = *(const float4*)&Ps[k * ASTR + ty * 4];
            *(float4*)&vv[0] = *(const float4*)&Vs[k * ASTR + tx * 4];
#pragma unroll
            for (int i = 0; i < 4; i++)
#pragma unroll
                for (int j = 0; j < 4; j++)
                    O[i][j] += pv[i] * vv[j];
        }
    }

    float lf = l_run;
    lf += __shfl_xor_sync(0xffffffffu, lf, 1);
    lf += __shfl_xor_sync(0xffffffffu, lf, 2);
    if (part == 0) lrow[r] = lf;
    __syncthreads();

#pragma unroll
    for (int i = 0; i < 4; i++) {
        const int q = qt * 64 + ty * 4 + i;
        const float inv = 1.0f / lrow[ty * 4 + i];
        float4 o;
        o.x = O[i][0] * inv;
        o.y = O[i][1] * inv;
        o.z = O[i][2] * inv;
        o.w = O[i][3] * inv;
        *(float4*)&ctx[((size_t)b * SS + q) * HH + nh * HD + tx * 4] = o;
    }
}

// ---------------------------------------------------------------------------
// LayerNorm / pool / final gemm
// ---------------------------------------------------------------------------
__global__ void __launch_bounds__(256) ln_kernel(
    const float* __restrict__ in, const float* __restrict__ gamma,
    const float* __restrict__ beta, float* __restrict__ out)
{
    const int row = blockIdx.x;
    const float* x = in + (size_t)row * HH;
    __shared__ float red[256];
    __shared__ float s_mean, s_rstd;
    const int tid = threadIdx.x;

    float s = 0.0f;
#pragma unroll
    for (int i = tid; i < HH; i += 256) s += x[i];
    red[tid] = s;
    __syncthreads();
    for (int off = 128; off > 0; off >>= 1) {
        if (tid < off) red[tid] += red[tid + off];
        __syncthreads();
    }
    if (tid == 0) s_mean = red[0] * (1.0f / HH);
    __syncthreads();
    const float mean = s_mean;

    float v = 0.0f;
#pragma unroll
    for (int i = tid; i < HH; i += 256) {
        const float d = x[i] - mean;
        v += d * d;
    }
    red[tid] = v;
    __syncthreads();
    for (int off = 128; off > 0; off >>= 1) {
        if (tid < off) red[tid] += red[tid + off];
        __syncthreads();
    }
    if (tid == 0) s_rstd = rsqrtf(red[0] * (1.0f / HH) + 1e-5f);
    __syncthreads();
    const float rstd = s_rstd;

#pragma unroll
    for (int i = tid; i < HH; i += 256)
        out[(size_t)row * HH + i] = (x[i] - mean) * rstd * gamma[i] + beta[i];
}

__global__ void __launch_bounds__(256) pool_kernel(
    const float* __restrict__ h, float* __restrict__ pooled)
{
    const int j = blockIdx.x * 256 + threadIdx.x;
    const int b = blockIdx.y;
    float s = 0.0f;
#pragma unroll 8
    for (int ss = 0; ss < SS; ss++)
        s += h[((size_t)b * SS + ss) * HH + j];
    pooled[b * HH + j] = s * (1.0f / SS);
}

__global__ void __launch_bounds__(256) final_gemm_kernel(
    const float* __restrict__ pooled, const float* __restrict__ W,
    const float* __restrict__ bias, float* __restrict__ out)
{
    __shared__ float pr[HH];
    const int b   = blockIdx.y;
    const int col = blockIdx.x * 256 + threadIdx.x;
    for (int i = threadIdx.x; i < HH; i += 256) pr[i] = pooled[b * HH + i];
    __syncthreads();
    float s = bias[col];
#pragma unroll 8
    for (int k = 0; k < HH; k++)
        s += pr[k] * W[(size_t)k * HH + col];
    out[b * HH + col] = s;
}

// ---------------------------------------------------------------------------
// Launch
// ---------------------------------------------------------------------------
extern "C" void kernel_launch(void* const* d_in, const int* in_sizes, int n_in,
                              void* d_out, int out_size)
{
    const float* x     = (const float*)d_in[0];
    const float* W_in  = (const float*)d_in[1];
    const float* b_in  = (const float*)d_in[2];
    const float* W_qkv = (const float*)d_in[3];
    const float* b_qkv = (const float*)d_in[4];
    const float* W_o   = (const float*)d_in[5];
    const float* b_o   = (const float*)d_in[6];
    const float* g1    = (const float*)d_in[7];
    const float* be1   = (const float*)d_in[8];
    const float* W_out = (const float*)d_in[9];
    const float* b_out = (const float*)d_in[10];
    const float* g2    = (const float*)d_in[11];
    const float* be2   = (const float*)d_in[12];
    float* out = (float*)d_out;

    float *h, *qkv, *ctx, *tmp, *pool, *fin;
    cudaGetSymbolAddress((void**)&h,    g_h);
    cudaGetSymbolAddress((void**)&qkv,  g_qkv);
    cudaGetSymbolAddress((void**)&ctx,  g_ctx);
    cudaGetSymbolAddress((void**)&tmp,  g_tmp);
    cudaGetSymbolAddress((void**)&pool, g_pool);
    cudaGetSymbolAddress((void**)&fin,  g_fin);

    __nv_bfloat16 *ah, *al, *wh, *wl;
    cudaGetSymbolAddress((void**)&ah, g_ah);
    cudaGetSymbolAddress((void**)&al, g_al);
    cudaGetSymbolAddress((void**)&wh, g_wh);
    cudaGetSymbolAddress((void**)&wl, g_wl);

    const size_t off_win  = 0;
    const size_t off_wqkv = (size_t)DIN * HH;
    const size_t off_wo   = off_wqkv + (size_t)NLAYER * HH * 3 * HH;

    const int attn_smem = (4 * 64 * ASTR + 128) * sizeof(float);
    cudaFuncSetAttribute(attn_kernel, cudaFuncAttributeMaxDynamicSharedMemorySize, attn_smem);
    cudaFuncSetAttribute(mma_gemm_kernel, cudaFuncAttributeMaxDynamicSharedMemorySize, MM_SMEM);

    // 0. split/transpose weights (bf16 hi/lo, [N][K])
    transpose_split_kernel<<<dim3(HH / 32, DIN / 32), dim3(32, 8)>>>(
        W_in, wh + off_win, wl + off_win, DIN, HH);
    for (int l = 0; l < NLAYER; l++) {
        transpose_split_kernel<<<dim3(3 * HH / 32, HH / 32), dim3(32, 8)>>>(
            W_qkv + (size_t)l * HH * 3 * HH,
            wh + off_wqkv + (size_t)l * 3 * HH * HH,
            wl + off_wqkv + (size_t)l * 3 * HH * HH, HH, 3 * HH);
        transpose_split_kernel<<<dim3(HH / 32, HH / 32), dim3(32, 8)>>>(
            W_o + (size_t)l * HH * HH,
            wh + off_wo + (size_t)l * HH * HH,
            wl + off_wo + (size_t)l * HH * HH, HH, HH);
    }

    // 1. input projection: h = x @ W_in + b_in
    {
        const int n4 = MROWS * DIN / 4;
        split_act_kernel<<<(n4 + 255) / 256, 256>>>(x, ah, al, n4);
        mma_gemm_kernel<<<dim3(HH / MBN, MROWS / MBM), 256, MM_SMEM>>>(
            ah, al, wh + off_win, wl + off_win, b_in, nullptr, h,
            MROWS, HH, DIN, 0);
    }

    // 2. layers
    for (int l = 0; l < NLAYER; l++) {
        const __nv_bfloat16* WqH = wh + off_wqkv + (size_t)l * 3 * HH * HH;
        const __nv_bfloat16* WqL = wl + off_wqkv + (size_t)l * 3 * HH * HH;
        const __nv_bfloat16* WoH = wh + off_wo + (size_t)l * HH * HH;
        const __nv_bfloat16* WoL = wl + off_wo + (size_t)l * HH * HH;
        const float* bq = b_qkv + (size_t)l * 3 * HH;
        const float* bo = b_o + (size_t)l * HH;
        const float* gg = g1 + (size_t)l * HH;
        const float* bb = be1 + (size_t)l * HH;

        const int n4 = MROWS * HH / 4;
        split_act_kernel<<<(n4 + 255) / 256, 256>>>(h, ah, al, n4);
        mma_gemm_kernel<<<dim3(3 * HH / MBN, MROWS / MBM), 256, MM_SMEM>>>(
            ah, al, WqH, WqL, bq, nullptr, qkv, MROWS, 3 * HH, HH, 0);

        attn_kernel<<<dim3(SS / 64, NHEAD, BB), 256, attn_smem>>>(qkv, ctx);

        split_act_kernel<<<(n4 + 255) / 256, 256>>>(ctx, ah, al, n4);
        mma_gemm_kernel<<<dim3(HH / MBN, MROWS / MBM), 256, MM_SMEM>>>(
            ah, al, WoH, WoL, bo, h, tmp, MROWS, HH, HH, 1);

        ln_kernel<<<MROWS, 256>>>(tmp, gg, bb, h);
    }

    // 3. mean pool, final projection + LN
    pool_kernel<<<dim3(HH / 256, BB), 256>>>(h, pool);
    final_gemm_kernel<<<dim3(HH / 256, BB), 256>>>(pool, W_out, b_out, fin);
    ln_kernel<<<BB, 256>>>(fin, g2, be2, out);
}

// round 4
// speedup vs baseline: 2.1047x; 1.5369x over previous
#include <cuda_runtime.h>
#include <cuda_bf16.h>
#include <math.h>
#include <stdint.h>

// Problem constants
#define BB 8
#define SS 1024
#define DIN 512
#define HH 1024
#define NHEAD 16
#define HD 64
#define NLAYER 4
#define MROWS (BB * SS)   // 8192

// ---------------------------------------------------------------------------
// Scratch (device globals; no allocation allowed)
// ---------------------------------------------------------------------------
__device__ float g_h[MROWS * HH];          // fp32 activations (residual)
__device__ float g_tmp[MROWS * HH];        // pre-LN
__device__ float g_pool[BB * HH];
__device__ float g_fin[BB * HH];

// split bf16 buffers
__device__ __nv_bfloat16 g_ah[MROWS * HH];       // x split hi
__device__ __nv_bfloat16 g_al[MROWS * HH];       // x split lo
__device__ __nv_bfloat16 g_hh[MROWS * HH];       // h split hi
__device__ __nv_bfloat16 g_hl[MROWS * HH];       // h split lo
__device__ __nv_bfloat16 g_qh[MROWS * 3 * HH];   // qkv split hi
__device__ __nv_bfloat16 g_ql[MROWS * 3 * HH];   // qkv split lo
__device__ __nv_bfloat16 g_ch[MROWS * HH];       // ctx split hi
__device__ __nv_bfloat16 g_cl[MROWS * HH];       // ctx split lo

#define W_TOTAL (DIN * HH + NLAYER * HH * 3 * HH + NLAYER * HH * HH)
__device__ __nv_bfloat16 g_wh[W_TOTAL];
__device__ __nv_bfloat16 g_wl[W_TOTAL];

// ---------------------------------------------------------------------------
// PTX wrappers (sm_80-portable)
// ---------------------------------------------------------------------------
__device__ __forceinline__ uint32_t smem_u32(const void* p) {
    uint32_t a;
    asm("{ .reg .u64 t; cvta.to.shared.u64 t, %1; cvt.u32.u64 %0, t; }"
        : "=r"(a) : "l"(p));
    return a;
}
__device__ __forceinline__ void cp_async16(uint32_t dst, const void* src) {
    asm volatile("cp.async.cg.shared.global [%0], [%1], 16;" :: "r"(dst), "l"(src));
}
__device__ __forceinline__ void cp_commit() {
    asm volatile("cp.async.commit_group;");
}
template <int N>
__device__ __forceinline__ void cp_wait() {
    asm volatile("cp.async.wait_group %0;" :: "n"(N));
}
__device__ __forceinline__ void ldsm_x4(uint32_t addr, uint32_t r[4]) {
    asm volatile("ldmatrix.sync.aligned.m8n8.x4.shared.b16 {%0,%1,%2,%3}, [%4];"
                 : "=r"(r[0]), "=r"(r[1]), "=r"(r[2]), "=r"(r[3]) : "r"(addr));
}
__device__ __forceinline__ void ldsm_x4_t(uint32_t addr, uint32_t r[4]) {
    asm volatile("ldmatrix.sync.aligned.m8n8.x4.trans.shared.b16 {%0,%1,%2,%3}, [%4];"
                 : "=r"(r[0]), "=r"(r[1]), "=r"(r[2]), "=r"(r[3]) : "r"(addr));
}
__device__ __forceinline__ void mma_bf16(
    float c[4], const uint32_t a[4], const uint32_t b0, const uint32_t b1)
{
    asm volatile(
        "mma.sync.aligned.m16n8k16.row.col.f32.bf16.bf16.f32 "
        "{%0,%1,%2,%3}, {%4,%5,%6,%7}, {%8,%9}, {%0,%1,%2,%3};"
        : "+f"(c[0]), "+f"(c[1]), "+f"(c[2]), "+f"(c[3])
        : "r"(a[0]), "r"(a[1]), "r"(a[2]), "r"(a[3]), "r"(b0), "r"(b1));
}

__device__ __forceinline__ void split2(float a, float b, uint32_t& hi, uint32_t& lo) {
    __nv_bfloat16 ha = __float2bfloat16(a), hb = __float2bfloat16(b);
    __nv_bfloat162 h2; h2.x = ha; h2.y = hb;
    hi = *(uint32_t*)&h2;
    __nv_bfloat162 l2;
    l2.x = __float2bfloat16(a - __bfloat162float(ha));
    l2.y = __float2bfloat16(b - __bfloat162float(hb));
    lo = *(uint32_t*)&l2;
}

// ---------------------------------------------------------------------------
// Weight transpose + split: W[K,N] fp32 -> Wt hi/lo [N,K] bf16
// ---------------------------------------------------------------------------
__global__ void transpose_split_kernel(
    const float* __restrict__ W,
    __nv_bfloat16* __restrict__ Th, __nv_bfloat16* __restrict__ Tl,
    int K, int N)
{
    __shared__ float tile[32][33];
    const int k0 = blockIdx.y * 32;
    const int n0 = blockIdx.x * 32;
    const int tx = threadIdx.x;
    const int ty = threadIdx.y;
#pragma unroll
    for (int r = 0; r < 32; r += 8)
        tile[ty + r][tx] = W[(size_t)(k0 + ty + r) * N + n0 + tx];
    __syncthreads();
#pragma unroll
    for (int r = 0; r < 32; r += 8) {
        const float v = tile[tx][ty + r];
        const __nv_bfloat16 h = __float2bfloat16(v);
        const float lo = v - __bfloat162float(h);
        const size_t o = (size_t)(n0 + ty + r) * K + k0 + tx;
        Th[o] = h;
        Tl[o] = __float2bfloat16(lo);
    }
}

// ---------------------------------------------------------------------------
// Activation split (for x only now)
// ---------------------------------------------------------------------------
__global__ void split_act_kernel(
    const float* __restrict__ in,
    __nv_bfloat16* __restrict__ hi, __nv_bfloat16* __restrict__ lo, int n4)
{
    const int i = blockIdx.x * 256 + threadIdx.x;
    if (i >= n4) return;
    const float4 v = ((const float4*)in)[i];
    uint32_t h0, l0, h1, l1;
    split2(v.x, v.y, h0, l0);
    split2(v.z, v.w, h1, l1);
    ((uint32_t*)hi)[i * 2]     = h0;
    ((uint32_t*)hi)[i * 2 + 1] = h1;
    ((uint32_t*)lo)[i * 2]     = l0;
    ((uint32_t*)lo)[i * 2 + 1] = l1;
}

// ---------------------------------------------------------------------------
// Split-bf16 HMMA GEMM: C = (Ah+Al)[M,K] @ (Bh+Bl)[N,K]^T + bias (+res)
// mode bit0: write fp32 Cf; bit1: write split Ch/Cl.
// ---------------------------------------------------------------------------
#define MBM 128
#define MBN 128
#define MBK 32
#define MSTR 40
#define MTILE (128 * MSTR * 2)
#define MSTAGE (4 * MTILE)
#define MM_SMEM (2 * MSTAGE)

__global__ void __launch_bounds__(256)
mma_gemm_kernel(
    const __nv_bfloat16* __restrict__ Ah, const __nv_bfloat16* __restrict__ Al,
    const __nv_bfloat16* __restrict__ Bh, const __nv_bfloat16* __restrict__ Bl,
    const float* __restrict__ bias, const float* __restrict__ res,
    float* __restrict__ Cf,
    __nv_bfloat16* __restrict__ Ch, __nv_bfloat16* __restrict__ Cl,
    int M, int N, int K, int hasRes, int mode)
{
    extern __shared__ __align__(16) char smem[];
    const uint32_t sbase = smem_u32(smem);

    const int t    = threadIdx.x;
    const int wid  = t >> 5;
    const int lane = t & 31;
    const int m0 = blockIdx.y * MBM;
    const int n0 = blockIdx.x * MBN;

    const int warp_m = (wid >> 2) * 64;
    const int warp_n = (wid & 3) * 32;

    const int crow  = t >> 1;
    const int cq    = (t & 1) * 2;

    const __nv_bfloat16* gsrc[4];
    gsrc[0] = Ah + (size_t)(m0 + crow) * K;
    gsrc[1] = Al + (size_t)(m0 + crow) * K;
    gsrc[2] = Bh + (size_t)(n0 + crow) * K;
    gsrc[3] = Bl + (size_t)(n0 + crow) * K;
    const uint32_t sdst_row = crow * (MSTR * 2);

    const int nc = K / MBK;

    {
#pragma unroll
        for (int tl = 0; tl < 4; tl++) {
            const uint32_t d = sbase + tl * MTILE + sdst_row;
            cp_async16(d + (cq + 0) * 16, gsrc[tl] + (cq + 0) * 8);
            cp_async16(d + (cq + 1) * 16, gsrc[tl] + (cq + 1) * 8);
        }
        cp_commit();
    }

    float acc[4][4][4];
#pragma unroll
    for (int mi = 0; mi < 4; mi++)
#pragma unroll
        for (int ni = 0; ni < 4; ni++)
#pragma unroll
            for (int r = 0; r < 4; r++) acc[mi][ni][r] = 0.0f;

    const int lrow = lane & 15;
    const int lcolq = (lane >> 4) << 3;

    for (int c = 0; c < nc; c++) {
        const int st = c & 1;
        if (c + 1 < nc) {
            const int k0 = (c + 1) * MBK;
            const uint32_t so = ((c + 1) & 1) * MSTAGE;
#pragma unroll
            for (int tl = 0; tl < 4; tl++) {
                const uint32_t d = sbase + so + tl * MTILE + sdst_row;
                cp_async16(d + (cq + 0) * 16, gsrc[tl] + k0 + (cq + 0) * 8);
                cp_async16(d + (cq + 1) * 16, gsrc[tl] + k0 + (cq + 1) * 8);
            }
            cp_commit();
            cp_wait<1>();
        } else {
            cp_wait<0>();
        }
        __syncthreads();

        const uint32_t sAh = sbase + st * MSTAGE + 0 * MTILE;
        const uint32_t sAl = sbase + st * MSTAGE + 1 * MTILE;
        const uint32_t sBh = sbase + st * MSTAGE + 2 * MTILE;
        const uint32_t sBl = sbase + st * MSTAGE + 3 * MTILE;

#pragma unroll
        for (int ks = 0; ks < 2; ks++) {
            const int col = ks * 16 + lcolq;
            uint32_t afh[4][4], afl[4][4];
#pragma unroll
            for (int mi = 0; mi < 4; mi++) {
                const uint32_t off =
                    (uint32_t)(warp_m + mi * 16 + lrow) * (MSTR * 2) + col * 2;
                ldsm_x4(sAh + off, afh[mi]);
                ldsm_x4(sAl + off, afl[mi]);
            }
            uint32_t bfh[4][2], bfl[4][2];
#pragma unroll
            for (int n2 = 0; n2 < 2; n2++) {
                const uint32_t off =
                    (uint32_t)(warp_n + n2 * 16 + lrow) * (MSTR * 2) + col * 2;
                uint32_t r4[4];
                ldsm_x4(sBh + off, r4);
                bfh[n2 * 2 + 0][0] = r4[0]; bfh[n2 * 2 + 1][0] = r4[1];
                bfh[n2 * 2 + 0][1] = r4[2]; bfh[n2 * 2 + 1][1] = r4[3];
                ldsm_x4(sBl + off, r4);
                bfl[n2 * 2 + 0][0] = r4[0]; bfl[n2 * 2 + 1][0] = r4[1];
                bfl[n2 * 2 + 0][1] = r4[2]; bfl[n2 * 2 + 1][1] = r4[3];
            }
#pragma unroll
            for (int mi = 0; mi < 4; mi++)
#pragma unroll
                for (int ni = 0; ni < 4; ni++) {
                    mma_bf16(acc[mi][ni], afh[mi], bfh[ni][0], bfh[ni][1]);
                    mma_bf16(acc[mi][ni], afh[mi], bfl[ni][0], bfl[ni][1]);
                    mma_bf16(acc[mi][ni], afl[mi], bfh[ni][0], bfh[ni][1]);
                }
        }
        __syncthreads();
    }

    const int g  = lane >> 2;
    const int tg = lane & 3;
#pragma unroll
    for (int mi = 0; mi < 4; mi++) {
#pragma unroll
        for (int ni = 0; ni < 4; ni++) {
            const int colg = n0 + warp_n + ni * 8 + tg * 2;
            const float bx = bias[colg], by = bias[colg + 1];
            const int r0 = m0 + warp_m + mi * 16 + g;
            const int r1 = r0 + 8;
            float2 o0, o1;
            o0.x = acc[mi][ni][0] + bx; o0.y = acc[mi][ni][1] + by;
            o1.x = acc[mi][ni][2] + bx; o1.y = acc[mi][ni][3] + by;
            if (hasRes) {
                const float2 v0 = *(const float2*)(res + (size_t)r0 * N + colg);
                const float2 v1 = *(const float2*)(res + (size_t)r1 * N + colg);
                o0.x += v0.x; o0.y += v0.y;
                o1.x += v1.x; o1.y += v1.y;
            }
            if (mode & 1) {
                *(float2*)(Cf + (size_t)r0 * N + colg) = o0;
                *(float2*)(Cf + (size_t)r1 * N + colg) = o1;
            }
            if (mode & 2) {
                uint32_t hi, lo;
                split2(o0.x, o0.y, hi, lo);
                *(uint32_t*)(Ch + (size_t)r0 * N + colg) = hi;
                *(uint32_t*)(Cl + (size_t)r0 * N + colg) = lo;
                split2(o1.x, o1.y, hi, lo);
                *(uint32_t*)(Ch + (size_t)r1 * N + colg) = hi;
                *(uint32_t*)(Cl + (size_t)r1 * N + colg) = lo;
            }
        }
    }
}

// ---------------------------------------------------------------------------
// Tensor-core flash attention, split-bf16 operands.
// qkv split (qh/ql) layout [B,S,3*HH]; ctx split out (cth/ctl) [B*S, HH].
// CTA: 128 threads (4 warps), 64 q-rows, K-tiles of 64.
// ---------------------------------------------------------------------------
#define APAD 144                            // bytes per 64-elem bf16 row (padded)
#define ATILE (64 * APAD)                   // 9216 B
#define AQ_H 0
#define AQ_L ATILE
#define AST0 (2 * ATILE)                    // stages start
#define ASTG (4 * ATILE)                    // Kh,Kl,Vh,Vl per stage = 36864
#define AT_SMEM (2 * ATILE + 2 * ASTG)      // 92160

__global__ void __launch_bounds__(128)
attn_mma_kernel(
    const __nv_bfloat16* __restrict__ qh, const __nv_bfloat16* __restrict__ ql,
    __nv_bfloat16* __restrict__ cth, __nv_bfloat16* __restrict__ ctl)
{
    extern __shared__ __align__(16) char smem[];
    const uint32_t sbase = smem_u32(smem);

    const int b  = blockIdx.z;
    const int nh = blockIdx.y;
    const int qt = blockIdx.x;
    const int t  = threadIdx.x;
    const int wid  = t >> 5;
    const int lane = t & 31;
    const int g  = lane >> 2;
    const int tg = lane & 3;
    const int lrow  = lane & 15;
    const int lcolq = (lane >> 4) << 3;

    const size_t bS = (size_t)b * SS;
    const int hoff = nh * HD;

    // --- copy indexing: row = t/2, quads (t&1)*4 .. +3
    const int crow = t >> 1;
    const int cq0  = (t & 1) * 4;

    // Q tiles (hi/lo)
    {
        const size_t grow = (bS + qt * 64 + crow) * (3 * HH) + hoff;
        const uint32_t d = sbase + crow * APAD + cq0 * 16;
#pragma unroll
        for (int i = 0; i < 4; i++) {
            cp_async16(d + AQ_H + i * 16, qh + grow + (cq0 + i) * 8);
            cp_async16(d + AQ_L + i * 16, ql + grow + (cq0 + i) * 8);
        }
    }
    // stage 0 K/V
    {
        const size_t grow = (bS + 0 * 64 + crow) * (3 * HH) + hoff;
        const uint32_t d = sbase + AST0 + crow * APAD + cq0 * 16;
#pragma unroll
        for (int i = 0; i < 4; i++) {
            cp_async16(d + 0 * ATILE + i * 16, qh + grow + HH + (cq0 + i) * 8);
            cp_async16(d + 1 * ATILE + i * 16, ql + grow + HH + (cq0 + i) * 8);
            cp_async16(d + 2 * ATILE + i * 16, qh + grow + 2 * HH + (cq0 + i) * 8);
            cp_async16(d + 3 * ATILE + i * 16, ql + grow + 2 * HH + (cq0 + i) * 8);
        }
    }
    cp_commit();
    // stage 1 K/V
    {
        const size_t grow = (bS + 1 * 64 + crow) * (3 * HH) + hoff;
        const uint32_t d = sbase + AST0 + ASTG + crow * APAD + cq0 * 16;
#pragma unroll
        for (int i = 0; i < 4; i++) {
            cp_async16(d + 0 * ATILE + i * 16, qh + grow + HH + (cq0 + i) * 8);
            cp_async16(d + 1 * ATILE + i * 16, ql + grow + HH + (cq0 + i) * 8);
            cp_async16(d + 2 * ATILE + i * 16, qh + grow + 2 * HH + (cq0 + i) * 8);
            cp_async16(d + 3 * ATILE + i * 16, ql + grow + 2 * HH + (cq0 + i) * 8);
        }
    }
    cp_commit();

    float acc_o[8][4];
#pragma unroll
    for (int nb = 0; nb < 8; nb++)
#pragma unroll
        for (int r = 0; r < 4; r++) acc_o[nb][r] = 0.0f;

    uint32_t aqh[4][4], aql[4][4];
    float m0 = -INFINITY, m1 = -INFINITY;
    float l0 = 0.0f, l1 = 0.0f;
    const float SC = 0.125f;

    for (int kt = 0; kt < SS / 64; kt++) {
        if (kt == SS / 64 - 1) { cp_wait<0>(); } else { cp_wait<1>(); }
        __syncthreads();

        if (kt == 0) {
            // Q fragments (once): A-operand m16k16, rows = warp's 16 q-rows
#pragma unroll
            for (int kb = 0; kb < 4; kb++) {
                const uint32_t off =
                    (uint32_t)(wid * 16 + lrow) * APAD + (kb * 16 + lcolq) * 2;
                ldsm_x4(sbase + AQ_H + off, aqh[kb]);
                ldsm_x4(sbase + AQ_L + off, aql[kb]);
            }
        }

        const uint32_t sK_h = sbase + AST0 + (kt & 1) * ASTG + 0 * ATILE;
        const uint32_t sK_l = sbase + AST0 + (kt & 1) * ASTG + 1 * ATILE;
        const uint32_t sV_h = sbase + AST0 + (kt & 1) * ASTG + 2 * ATILE;
        const uint32_t sV_l = sbase + AST0 + (kt & 1) * ASTG + 3 * ATILE;

        // ---- scores: acc_s[8][4]
        float s[8][4];
#pragma unroll
        for (int nb = 0; nb < 8; nb++)
#pragma unroll
            for (int r = 0; r < 4; r++) s[nb][r] = 0.0f;

#pragma unroll
        for (int n2 = 0; n2 < 4; n2++) {
#pragma unroll
            for (int kb = 0; kb < 4; kb++) {
                const uint32_t off =
                    (uint32_t)(n2 * 16 + lrow) * APAD + (kb * 16 + lcolq) * 2;
                uint32_t kh4[4], kl4[4];
                ldsm_x4(sK_h + off, kh4);
                ldsm_x4(sK_l + off, kl4);
                mma_bf16(s[n2 * 2 + 0], aqh[kb], kh4[0], kh4[2]);
                mma_bf16(s[n2 * 2 + 1], aqh[kb], kh4[1], kh4[3]);
                mma_bf16(s[n2 * 2 + 0], aqh[kb], kl4[0], kl4[2]);
                mma_bf16(s[n2 * 2 + 1], aqh[kb], kl4[1], kl4[3]);
                mma_bf16(s[n2 * 2 + 0], aql[kb], kh4[0], kh4[2]);
                mma_bf16(s[n2 * 2 + 1], aql[kb], kh4[1], kh4[3]);
            }
        }

        // ---- online softmax on fragments (rows g and g+8)
        float mx0 = -INFINITY, mx1 = -INFINITY;
#pragma unroll
        for (int nb = 0; nb < 8; nb++) {
            s[nb][0] *= SC; s[nb][1] *= SC; s[nb][2] *= SC; s[nb][3] *= SC;
            mx0 = fmaxf(mx0, fmaxf(s[nb][0], s[nb][1]));
            mx1 = fmaxf(mx1, fmaxf(s[nb][2], s[nb][3]));
        }
        mx0 = fmaxf(mx0, __shfl_xor_sync(0xffffffffu, mx0, 1));
        mx0 = fmaxf(mx0, __shfl_xor_sync(0xffffffffu, mx0, 2));
        mx1 = fmaxf(mx1, __shfl_xor_sync(0xffffffffu, mx1, 1));
        mx1 = fmaxf(mx1, __shfl_xor_sync(0xffffffffu, mx1, 2));
        const float mn0 = fmaxf(m0, mx0);
        const float mn1 = fmaxf(m1, mx1);
        const float f0 = __expf(m0 - mn0);
        const float f1 = __expf(m1 - mn1);
        m0 = mn0; m1 = mn1;
        l0 *= f0; l1 *= f1;
#pragma unroll
        for (int nb = 0; nb < 8; nb++) {
            s[nb][0] = __expf(s[nb][0] - mn0);
            s[nb][1] = __expf(s[nb][1] - mn0);
            s[nb][2] = __expf(s[nb][2] - mn1);
            s[nb][3] = __expf(s[nb][3] - mn1);
            l0 += s[nb][0] + s[nb][1];
            l1 += s[nb][2] + s[nb][3];
            acc_o[nb][0] *= f0; acc_o[nb][1] *= f0;
            acc_o[nb][2] *= f1; acc_o[nb][3] *= f1;
        }

        // ---- P fragments (m16k16 A-operand), hi/lo split
        uint32_t ph[4][4], pl[4][4];
#pragma unroll
        for (int kb = 0; kb < 4; kb++) {
            split2(s[2 * kb][0],     s[2 * kb][1],     ph[kb][0], pl[kb][0]);
            split2(s[2 * kb][2],     s[2 * kb][3],     ph[kb][1], pl[kb][1]);
            split2(s[2 * kb + 1][0], s[2 * kb + 1][1], ph[kb][2], pl[kb][2]);
            split2(s[2 * kb + 1][2], s[2 * kb + 1][3], ph[kb][3], pl[kb][3]);
        }

        // ---- O += P @ V  (V via ldmatrix.trans)
#pragma unroll
        for (int kb = 0; kb < 4; kb++) {
#pragma unroll
            for (int n2 = 0; n2 < 4; n2++) {
                const uint32_t off =
                    (uint32_t)(kb * 16 + lrow) * APAD + (n2 * 16 + lcolq) * 2;
                uint32_t vh4[4], vl4[4];
                ldsm_x4_t(sV_h + off, vh4);
                ldsm_x4_t(sV_l + off, vl4);
                mma_bf16(acc_o[n2 * 2 + 0], ph[kb], vh4[0], vh4[1]);
                mma_bf16(acc_o[n2 * 2 + 1], ph[kb], vh4[2], vh4[3]);
                mma_bf16(acc_o[n2 * 2 + 0], ph[kb], vl4[0], vl4[1]);
                mma_bf16(acc_o[n2 * 2 + 1], ph[kb], vl4[2], vl4[3]);
                mma_bf16(acc_o[n2 * 2 + 0], pl[kb], vh4[0], vh4[1]);
                mma_bf16(acc_o[n2 * 2 + 1], pl[kb], vh4[2], vh4[3]);
            }
        }

        __syncthreads();
        // prefetch stage for kt+2 into buffer (kt&1)
        if (kt + 2 < SS / 64) {
            const size_t grow = (bS + (kt + 2) * 64 + crow) * (3 * HH) + hoff;
            const uint32_t d = sbase + AST0 + (kt & 1) * ASTG + crow * APAD + cq0 * 16;
#pragma unroll
            for (int i = 0; i < 4; i++) {
                cp_async16(d + 0 * ATILE + i * 16, qh + grow + HH + (cq0 + i) * 8);
                cp_async16(d + 1 * ATILE + i * 16, ql + grow + HH + (cq0 + i) * 8);
                cp_async16(d + 2 * ATILE + i * 16, qh + grow + 2 * HH + (cq0 + i) * 8);
                cp_async16(d + 3 * ATILE + i * 16, ql + grow + 2 * HH + (cq0 + i) * 8);
            }
        }
        cp_commit();
    }

    // finalize l across quad and write ctx split
    l0 += __shfl_xor_sync(0xffffffffu, l0, 1);
    l0 += __shfl_xor_sync(0xffffffffu, l0, 2);
    l1 += __shfl_xor_sync(0xffffffffu, l1, 1);
    l1 += __shfl_xor_sync(0xffffffffu, l1, 2);
    const float inv0 = 1.0f / l0;
    const float inv1 = 1.0f / l1;

    const size_t r0 = bS + qt * 64 + wid * 16 + g;
    const size_t r1 = r0 + 8;
#pragma unroll
    for (int nb = 0; nb < 8; nb++) {
        const int col = hoff + nb * 8 + tg * 2;
        uint32_t hi, lo;
        split2(acc_o[nb][0] * inv0, acc_o[nb][1] * inv0, hi, lo);
        *(uint32_t*)(cth + r0 * HH + col) = hi;
        *(uint32_t*)(ctl + r0 * HH + col) = lo;
        split2(acc_o[nb][2] * inv1, acc_o[nb][3] * inv1, hi, lo);
        *(uint32_t*)(cth + r1 * HH + col) = hi;
        *(uint32_t*)(ctl + r1 * HH + col) = lo;
    }
}

// ---------------------------------------------------------------------------
// LayerNorm, optionally emitting bf16 hi/lo split of output
// ---------------------------------------------------------------------------
__global__ void __launch_bounds__(256) ln_kernel(
    const float* __restrict__ in, const float* __restrict__ gamma,
    const float* __restrict__ beta, float* __restrict__ out,
    __nv_bfloat16* __restrict__ outh, __nv_bfloat16* __restrict__ outl,
    int doSplit)
{
    const int row = blockIdx.x;
    const float* x = in + (size_t)row * HH;
    __shared__ float red[256];
    __shared__ float s_mean, s_rstd;
    const int tid = threadIdx.x;

    float s = 0.0f;
#pragma unroll
    for (int i = tid; i < HH; i += 256) s += x[i];
    red[tid] = s;
    __syncthreads();
    for (int off = 128; off > 0; off >>= 1) {
        if (tid < off) red[tid] += red[tid + off];
        __syncthreads();
    }
    if (tid == 0) s_mean = red[0] * (1.0f / HH);
    __syncthreads();
    const float mean = s_mean;

    float v = 0.0f;
#pragma unroll
    for (int i = tid; i < HH; i += 256) {
        const float d = x[i] - mean;
        v += d * d;
    }
    red[tid] = v;
    __syncthreads();
    for (int off = 128; off > 0; off >>= 1) {
        if (tid < off) red[tid] += red[tid + off];
        __syncthreads();
    }
    if (tid == 0) s_rstd = rsqrtf(red[0] * (1.0f / HH) + 1e-5f);
    __syncthreads();
    const float rstd = s_rstd;

    const int i0 = tid * 4;
    const float4 xv = *(const float4*)&x[i0];
    const float4 gv = *(const float4*)&gamma[i0];
    const float4 bv = *(const float4*)&beta[i0];
    float4 o;
    o.x = (xv.x - mean) * rstd * gv.x + bv.x;
    o.y = (xv.y - mean) * rstd * gv.y + bv.y;
    o.z = (xv.z - mean) * rstd * gv.z + bv.z;
    o.w = (xv.w - mean) * rstd * gv.w + bv.w;
    *(float4*)&out[(size_t)row * HH + i0] = o;
    if (doSplit) {
        uint32_t h0, lo0, h1, lo1;
        split2(o.x, o.y, h0, lo0);
        split2(o.z, o.w, h1, lo1);
        *(uint32_t*)(outh + (size_t)row * HH + i0)     = h0;
        *(uint32_t*)(outh + (size_t)row * HH + i0 + 2) = h1;
        *(uint32_t*)(outl + (size_t)row * HH + i0)     = lo0;
        *(uint32_t*)(outl + (size_t)row * HH + i0 + 2) = lo1;
    }
}

__global__ void __launch_bounds__(256) pool_kernel(
    const float* __restrict__ h, float* __restrict__ pooled)
{
    const int j = blockIdx.x * 256 + threadIdx.x;
    const int b = blockIdx.y;
    float s = 0.0f;
#pragma unroll 8
    for (int ss = 0; ss < SS; ss++)
        s += h[((size_t)b * SS + ss) * HH + j];
    pooled[b * HH + j] = s * (1.0f / SS);
}

__global__ void __launch_bounds__(256) final_gemm_kernel(
    const float* __restrict__ pooled, const float* __restrict__ W,
    const float* __restrict__ bias, float* __restrict__ out)
{
    __shared__ float pr[HH];
    const int b   = blockIdx.y;
    const int col = blockIdx.x * 256 + threadIdx.x;
    for (int i = threadIdx.x; i < HH; i += 256) pr[i] = pooled[b * HH + i];
    __syncthreads();
    float s = bias[col];
#pragma unroll 8
    for (int k = 0; k < HH; k++)
        s += pr[k] * W[(size_t)k * HH + col];
    out[b * HH + col] = s;
}

// ---------------------------------------------------------------------------
// Launch
// ---------------------------------------------------------------------------
extern "C" void kernel_launch(void* const* d_in, const int* in_sizes, int n_in,
                              void* d_out, int out_size)
{
    const float* x     = (const float*)d_in[0];
    const float* W_in  = (const float*)d_in[1];
    const float* b_in  = (const float*)d_in[2];
    const float* W_qkv = (const float*)d_in[3];
    const float* b_qkv = (const float*)d_in[4];
    const float* W_o   = (const float*)d_in[5];
    const float* b_o   = (const float*)d_in[6];
    const float* g1    = (const float*)d_in[7];
    const float* be1   = (const float*)d_in[8];
    const float* W_out = (const float*)d_in[9];
    const float* b_out = (const float*)d_in[10];
    const float* g2    = (const float*)d_in[11];
    const float* be2   = (const float*)d_in[12];
    float* out = (float*)d_out;

    float *h, *tmp, *pool, *fin;
    cudaGetSymbolAddress((void**)&h,    g_h);
    cudaGetSymbolAddress((void**)&tmp,  g_tmp);
    cudaGetSymbolAddress((void**)&pool, g_pool);
    cudaGetSymbolAddress((void**)&fin,  g_fin);

    __nv_bfloat16 *ah, *al, *hh, *hl, *qh, *ql, *ch, *cl, *wh, *wl;
    cudaGetSymbolAddress((void**)&ah, g_ah);
    cudaGetSymbolAddress((void**)&al, g_al);
    cudaGetSymbolAddress((void**)&hh, g_hh);
    cudaGetSymbolAddress((void**)&hl, g_hl);
    cudaGetSymbolAddress((void**)&qh, g_qh);
    cudaGetSymbolAddress((void**)&ql, g_ql);
    cudaGetSymbolAddress((void**)&ch, g_ch);
    cudaGetSymbolAddress((void**)&cl, g_cl);
    cudaGetSymbolAddress((void**)&wh, g_wh);
    cudaGetSymbolAddress((void**)&wl, g_wl);

    const size_t off_win  = 0;
    const size_t off_wqkv = (size_t)DIN * HH;
    const size_t off_wo   = off_wqkv + (size_t)NLAYER * HH * 3 * HH;

    cudaFuncSetAttribute(mma_gemm_kernel, cudaFuncAttributeMaxDynamicSharedMemorySize, MM_SMEM);
    cudaFuncSetAttribute(attn_mma_kernel, cudaFuncAttributeMaxDynamicSharedMemorySize, AT_SMEM);

    // 0. split/transpose weights (bf16 hi/lo, [N][K])
    transpose_split_kernel<<<dim3(HH / 32, DIN / 32), dim3(32, 8)>>>(
        W_in, wh + off_win, wl + off_win, DIN, HH);
    for (int l = 0; l < NLAYER; l++) {
        transpose_split_kernel<<<dim3(3 * HH / 32, HH / 32), dim3(32, 8)>>>(
            W_qkv + (size_t)l * HH * 3 * HH,
            wh + off_wqkv + (size_t)l * 3 * HH * HH,
            wl + off_wqkv + (size_t)l * 3 * HH * HH, HH, 3 * HH);
        transpose_split_kernel<<<dim3(HH / 32, HH / 32), dim3(32, 8)>>>(
            W_o + (size_t)l * HH * HH,
            wh + off_wo + (size_t)l * HH * HH,
            wl + off_wo + (size_t)l * HH * HH, HH, HH);
    }

    // 1. split x; in-proj -> h fp32 + split (mode 3)
    {
        const int n4 = MROWS * DIN / 4;
        split_act_kernel<<<(n4 + 255) / 256, 256>>>(x, ah, al, n4);
        mma_gemm_kernel<<<dim3(HH / MBN, MROWS / MBM), 256, MM_SMEM>>>(
            ah, al, wh + off_win, wl + off_win, b_in, nullptr,
            h, hh, hl, MROWS, HH, DIN, 0, 3);
    }

    // 2. layers
    for (int l = 0; l < NLAYER; l++) {
        const __nv_bfloat16* WqH = wh + off_wqkv + (size_t)l * 3 * HH * HH;
        const __nv_bfloat16* WqL = wl + off_wqkv + (size_t)l * 3 * HH * HH;
        const __nv_bfloat16* WoH = wh + off_wo + (size_t)l * HH * HH;
        const __nv_bfloat16* WoL = wl + off_wo + (size_t)l * HH * HH;
        const float* bq = b_qkv + (size_t)l * 3 * HH;
        const float* bo = b_o + (size_t)l * HH;
        const float* gg = g1 + (size_t)l * HH;
        const float* bb = be1 + (size_t)l * HH;

        // qkv (split out only, mode 2)
        mma_gemm_kernel<<<dim3(3 * HH / MBN, MROWS / MBM), 256, MM_SMEM>>>(
            hh, hl, WqH, WqL, bq, nullptr,
            nullptr, qh, ql, MROWS, 3 * HH, HH, 0, 2);

        // attention -> ctx split
        attn_mma_kernel<<<dim3(SS / 64, NHEAD, BB), 128, AT_SMEM>>>(qh, ql, ch, cl);

        // o-proj + residual (fp32 out, mode 1)
        mma_gemm_kernel<<<dim3(HH / MBN, MROWS / MBM), 256, MM_SMEM>>>(
            ch, cl, WoH, WoL, bo, h,
            tmp, nullptr, nullptr, MROWS, HH, HH, 1, 1);

        // layernorm -> h fp32 + split
        ln_kernel<<<MROWS, 256>>>(tmp, gg, bb, h, hh, hl, 1);
    }

    // 3. mean pool, final projection + LN
    pool_kernel<<<dim3(HH / 256, BB), 256>>>(h, pool);
    final_gemm_kernel<<<dim3(HH / 256, BB), 256>>>(pool, W_out, b_out, fin);
    ln_kernel<<<BB, 256>>>(fin, g2, be2, out, nullptr, nullptr, 0);
}